// round 1
// baseline (speedup 1.0000x reference)
#include <cuda_runtime.h>
#include <math.h>

#define S_TOK 257
#define D_DIM 1024
#define HID 4096
#define NLAYER 12
#define NC 256
#define CSZ 128
#define AGE_V 258
#define OBS_N 2048
#define OUT_N 512
#define HEADS 16
#define DH 64

// ---------------- scratch (device globals; no allocation allowed) ----------
__device__ float g_x[S_TOK * D_DIM];
__device__ float g_q[S_TOK * D_DIM];
__device__ float g_k[S_TOK * D_DIM];
__device__ float g_v[S_TOK * D_DIM];
__device__ float g_ao[S_TOK * D_DIM];
__device__ float g_tmp[S_TOK * D_DIM];
__device__ float g_ffn[S_TOK * HID];

// ---------------- warp reduce helpers --------------------------------------
__device__ __forceinline__ float warpMax(float v) {
#pragma unroll
    for (int o = 16; o; o >>= 1) v = fmaxf(v, __shfl_xor_sync(0xffffffffu, v, o));
    return v;
}
__device__ __forceinline__ float warpSum(float v) {
#pragma unroll
    for (int o = 16; o; o >>= 1) v += __shfl_xor_sync(0xffffffffu, v, o);
    return v;
}

// ---------------- GEMM: C[M,N] = A[M,K] @ B[N,K]^T + bias (+res) (relu?) ---
// BM=64, BN=64, BK=32, 128 threads, 8x4 micro-tile.
#define BM 64
#define BN 64
#define BK 32
#define LDS_A 68

__global__ __launch_bounds__(128) void gemm_kernel(
    const float* __restrict__ A, const float* __restrict__ B,
    const float* __restrict__ bias, const float* __restrict__ res,
    float* __restrict__ C, int M, int N, int K, int relu_flag)
{
    __shared__ float As[BK * LDS_A];
    __shared__ float Bs[BK * LDS_A];

    const int tid = threadIdx.x;
    const int tx = tid & 15;        // 0..15 -> n micro (4 cols)
    const int ty = tid >> 4;        // 0..7  -> m micro (8 rows)
    const int bm = blockIdx.y * BM;
    const int bn = blockIdx.x * BN;

    float acc[8][4];
#pragma unroll
    for (int i = 0; i < 8; i++)
#pragma unroll
        for (int j = 0; j < 4; j++) acc[i][j] = 0.f;

    for (int k0 = 0; k0 < K; k0 += BK) {
        // load A tile (64 rows x 32 k) = 512 float4, 4 per thread; transpose to As[k][m]
#pragma unroll
        for (int i = 0; i < 4; i++) {
            int idx = tid + i * 128;
            int row = idx >> 3;
            int kq = (idx & 7) << 2;
            float4 a4;
            if (bm + row < M)
                a4 = *reinterpret_cast<const float4*>(A + (size_t)(bm + row) * K + k0 + kq);
            else
                a4 = make_float4(0.f, 0.f, 0.f, 0.f);
            As[(kq + 0) * LDS_A + row] = a4.x;
            As[(kq + 1) * LDS_A + row] = a4.y;
            As[(kq + 2) * LDS_A + row] = a4.z;
            As[(kq + 3) * LDS_A + row] = a4.w;
            float4 b4 = *reinterpret_cast<const float4*>(B + (size_t)(bn + row) * K + k0 + kq);
            Bs[(kq + 0) * LDS_A + row] = b4.x;
            Bs[(kq + 1) * LDS_A + row] = b4.y;
            Bs[(kq + 2) * LDS_A + row] = b4.z;
            Bs[(kq + 3) * LDS_A + row] = b4.w;
        }
        __syncthreads();

#pragma unroll
        for (int kk = 0; kk < BK; kk++) {
            const float4 a0 = *reinterpret_cast<const float4*>(&As[kk * LDS_A + ty * 8]);
            const float4 a1 = *reinterpret_cast<const float4*>(&As[kk * LDS_A + ty * 8 + 4]);
            const float4 b0 = *reinterpret_cast<const float4*>(&Bs[kk * LDS_A + tx * 4]);
            float am[8] = {a0.x, a0.y, a0.z, a0.w, a1.x, a1.y, a1.z, a1.w};
            float bv[4] = {b0.x, b0.y, b0.z, b0.w};
#pragma unroll
            for (int i = 0; i < 8; i++)
#pragma unroll
                for (int j = 0; j < 4; j++)
                    acc[i][j] = fmaf(am[i], bv[j], acc[i][j]);
        }
        __syncthreads();
    }

    const int nbase = bn + tx * 4;
    const float4 b4 = *reinterpret_cast<const float4*>(bias + nbase);
#pragma unroll
    for (int i = 0; i < 8; i++) {
        int m = bm + ty * 8 + i;
        if (m < M) {
            float4 r4 = make_float4(0.f, 0.f, 0.f, 0.f);
            if (res) r4 = *reinterpret_cast<const float4*>(res + (size_t)m * N + nbase);
            float4 o;
            o.x = acc[i][0] + b4.x + r4.x;
            o.y = acc[i][1] + b4.y + r4.y;
            o.z = acc[i][2] + b4.z + r4.z;
            o.w = acc[i][3] + b4.w + r4.w;
            if (relu_flag) {
                o.x = fmaxf(o.x, 0.f); o.y = fmaxf(o.y, 0.f);
                o.z = fmaxf(o.z, 0.f); o.w = fmaxf(o.w, 0.f);
            }
            *reinterpret_cast<float4*>(C + (size_t)m * N + nbase) = o;
        }
    }
}

// ---------------- matvec: out[n] = act(dot(W[n,:], x) + bias[n]) -----------
// 256 threads, 8 warps -> 8 outputs per block. act: 0 none, 1 relu, 2 tanh
__global__ __launch_bounds__(256) void matvec_kernel(
    const float* __restrict__ W, const float* __restrict__ bias,
    const float* __restrict__ x, float* __restrict__ out,
    int N, int K, int act)
{
    __shared__ float xs[OBS_N];
    const int tid = threadIdx.x;
    for (int i = tid; i < K; i += 256) xs[i] = x[i];
    __syncthreads();
    const int warp = tid >> 5, lane = tid & 31;
    const int n = blockIdx.x * 8 + warp;
    if (n >= N) return;
    const float4* wr = reinterpret_cast<const float4*>(W + (size_t)n * K);
    const float4* x4 = reinterpret_cast<const float4*>(xs);
    float s = 0.f;
    const int K4 = K >> 2;
    for (int kb = lane; kb < K4; kb += 32) {
        float4 w = wr[kb], xv = x4[kb];
        s += w.x * xv.x + w.y * xv.y + w.z * xv.z + w.w * xv.w;
    }
    s = warpSum(s);
    if (lane == 0) {
        s += bias[n];
        if (act == 1) s = fmaxf(s, 0.f);
        else if (act == 2) s = tanhf(s);
        out[n] = s;
    }
}

// ---------------- concept embedding (rows 1..256 of x) ---------------------
__global__ __launch_bounds__(256) void cemb_kernel(
    const float* __restrict__ concepts, const float* __restrict__ Wc,
    const float* __restrict__ bc, const float* __restrict__ Wage,
    const float* __restrict__ bage, float* __restrict__ x)
{
    const int i = blockIdx.x;           // concept 0..255 (token row i+1)
    const int tid = threadIdx.x;
    __shared__ float cv[CSZ];
    if (tid < CSZ) cv[tid] = concepts[i * CSZ + tid];
    __syncthreads();
    const float agef = (float)i / 256.0f;
    for (int d = tid; d < D_DIM; d += 256) {
        const float4* wr = reinterpret_cast<const float4*>(Wc + (size_t)d * CSZ);
        const float4* c4 = reinterpret_cast<const float4*>(cv);
        float s = 0.f;
#pragma unroll
        for (int t = 0; t < CSZ / 4; t++) {
            float4 w = wr[t], c = c4[t];
            s += w.x * c.x + w.y * c.y + w.z * c.z + w.w * c.w;
        }
        s += bc[d] + Wage[(size_t)d * AGE_V + i] + agef * Wage[(size_t)d * AGE_V + (AGE_V - 1)] + bage[d];
        x[(size_t)(i + 1) * D_DIM + d] = s;
    }
}

// ---------------- attention: one block per (query, head) -------------------
__global__ __launch_bounds__(256) void attn_kernel(
    const float* __restrict__ q, const float* __restrict__ k,
    const float* __restrict__ v, float* __restrict__ o)
{
    const int qi = blockIdx.x;
    const int h = blockIdx.y;
    const int tid = threadIdx.x;
    const int lane = tid & 31, warp = tid >> 5;

    __shared__ float qv[DH];
    __shared__ float sc[S_TOK];
    __shared__ float red[8];
    __shared__ float part[256];
    __shared__ float s_max, s_sum;

    if (tid < DH) qv[tid] = q[(size_t)qi * D_DIM + h * DH + tid];
    __syncthreads();

    float lmax = -1e30f;
    for (int j = tid; j < S_TOK; j += 256) {
        const float4* kr = reinterpret_cast<const float4*>(k + (size_t)j * D_DIM + h * DH);
        const float4* q4 = reinterpret_cast<const float4*>(qv);
        float s = 0.f;
#pragma unroll
        for (int t = 0; t < DH / 4; t++) {
            float4 kv = kr[t], qq = q4[t];
            s += kv.x * qq.x + kv.y * qq.y + kv.z * qq.z + kv.w * qq.w;
        }
        s *= 0.125f;
        sc[j] = s;
        lmax = fmaxf(lmax, s);
    }
    // block max
    lmax = warpMax(lmax);
    if (lane == 0) red[warp] = lmax;
    __syncthreads();
    if (warp == 0) {
        float t = (lane < 8) ? red[lane] : -1e30f;
        t = warpMax(t);
        if (lane == 0) s_max = t;
    }
    __syncthreads();
    const float mx = s_max;

    float lsum = 0.f;
    for (int j = tid; j < S_TOK; j += 256) {
        float e = __expf(sc[j] - mx);
        sc[j] = e;
        lsum += e;
    }
    lsum = warpSum(lsum);
    __syncthreads();          // protect red[] reuse
    if (lane == 0) red[warp] = lsum;
    __syncthreads();
    if (warp == 0) {
        float t = (lane < 8) ? red[lane] : 0.f;
        t = warpSum(t);
        if (lane == 0) s_sum = t;
    }
    __syncthreads();
    const float inv_sum = 1.0f / s_sum;

    // weighted sum over V: threads = 4 j-groups x 64 dims
    const int d = tid & 63, jg = tid >> 6;
    float acc = 0.f;
    for (int j = jg; j < S_TOK; j += 4)
        acc = fmaf(sc[j], v[(size_t)j * D_DIM + h * DH + d], acc);
    part[tid] = acc;
    __syncthreads();
    if (tid < DH) {
        float r = (part[tid] + part[64 + tid] + part[128 + tid] + part[192 + tid]) * inv_sum;
        o[(size_t)qi * D_DIM + h * DH + tid] = r;
    }
}

// ---------------- layernorm over rows --------------------------------------
__global__ __launch_bounds__(256) void ln_kernel(
    const float* __restrict__ in, const float* __restrict__ g,
    const float* __restrict__ b, float* __restrict__ out)
{
    const int r = blockIdx.x;
    const int tid = threadIdx.x;
    const int lane = tid & 31, warp = tid >> 5;
    __shared__ float rs[8], rs2[8];

    const float4 v4 = reinterpret_cast<const float4*>(in + (size_t)r * D_DIM)[tid];
    float s = v4.x + v4.y + v4.z + v4.w;
    float s2 = v4.x * v4.x + v4.y * v4.y + v4.z * v4.z + v4.w * v4.w;
    s = warpSum(s); s2 = warpSum(s2);
    if (lane == 0) { rs[warp] = s; rs2[warp] = s2; }
    __syncthreads();
    __shared__ float sm, sv;
    if (warp == 0) {
        float t = (lane < 8) ? rs[lane] : 0.f;
        float t2 = (lane < 8) ? rs2[lane] : 0.f;
        t = warpSum(t); t2 = warpSum(t2);
        if (lane == 0) {
            float mean = t * (1.0f / D_DIM);
            float var = t2 * (1.0f / D_DIM) - mean * mean;
            sm = mean;
            sv = rsqrtf(var + 1e-5f);
        }
    }
    __syncthreads();
    const float mean = sm, inv = sv;
    const int idx = tid * 4;
    const float4 g4 = reinterpret_cast<const float4*>(g)[tid];
    const float4 b4 = reinterpret_cast<const float4*>(b)[tid];
    float4 o;
    o.x = (v4.x - mean) * inv * g4.x + b4.x;
    o.y = (v4.y - mean) * inv * g4.y + b4.y;
    o.z = (v4.z - mean) * inv * g4.z + b4.z;
    o.w = (v4.w - mean) * inv * g4.w + b4.w;
    reinterpret_cast<float4*>(out + (size_t)r * D_DIM)[tid] = o;
    (void)idx;
}

// ---------------- host launch ----------------------------------------------
extern "C" void kernel_launch(void* const* d_in, const int* in_sizes, int n_in,
                              void* d_out, int out_size)
{
    const float* observation = (const float*)d_in[0];
    const float* concepts    = (const float*)d_in[1];
    const float* W_core = (const float*)d_in[2];
    const float* b_core = (const float*)d_in[3];
    const float* W_cemb = (const float*)d_in[4];
    const float* b_cemb = (const float*)d_in[5];
    const float* W_age  = (const float*)d_in[6];
    const float* b_age  = (const float*)d_in[7];
    const float* Wq = (const float*)d_in[8];
    const float* bq = (const float*)d_in[9];
    const float* Wk = (const float*)d_in[10];
    const float* bk = (const float*)d_in[11];
    const float* Wv = (const float*)d_in[12];
    const float* bv = (const float*)d_in[13];
    const float* Wo = (const float*)d_in[14];
    const float* bo = (const float*)d_in[15];
    const float* ln1_g = (const float*)d_in[16];
    const float* ln1_b = (const float*)d_in[17];
    const float* W1 = (const float*)d_in[18];
    const float* b1 = (const float*)d_in[19];
    const float* W2 = (const float*)d_in[20];
    const float* b2 = (const float*)d_in[21];
    const float* ln2_g = (const float*)d_in[22];
    const float* ln2_b = (const float*)d_in[23];
    const float* W_concept = (const float*)d_in[24];
    const float* b_concept = (const float*)d_in[25];
    const float* W_out = (const float*)d_in[26];
    const float* b_out = (const float*)d_in[27];

    float *x, *q, *k, *v, *ao, *tmp, *ffn;
    cudaGetSymbolAddress((void**)&x, g_x);
    cudaGetSymbolAddress((void**)&q, g_q);
    cudaGetSymbolAddress((void**)&k, g_k);
    cudaGetSymbolAddress((void**)&v, g_v);
    cudaGetSymbolAddress((void**)&ao, g_ao);
    cudaGetSymbolAddress((void**)&tmp, g_tmp);
    cudaGetSymbolAddress((void**)&ffn, g_ffn);

    const int M = S_TOK;
    const dim3 gemm_block(128);
    const dim3 grid_d(D_DIM / BN, (M + BM - 1) / BM);   // 16 x 5
    const dim3 grid_h(HID / BN, (M + BM - 1) / BM);     // 64 x 5

    // --- embeddings ---
    matvec_kernel<<<D_DIM / 8, 256>>>(W_core, b_core, observation, x, D_DIM, OBS_N, 0);
    cemb_kernel<<<NC, 256>>>(concepts, W_cemb, b_cemb, W_age, b_age, x);

    // --- transformer layers ---
    for (int l = 0; l < NLAYER; l++) {
        const size_t od = (size_t)l * D_DIM * D_DIM;
        const size_t ob = (size_t)l * D_DIM;
        const size_t o1w = (size_t)l * HID * D_DIM;
        const size_t o1b = (size_t)l * HID;

        gemm_kernel<<<grid_d, gemm_block>>>(x, Wq + od, bq + ob, nullptr, q, M, D_DIM, D_DIM, 0);
        gemm_kernel<<<grid_d, gemm_block>>>(x, Wk + od, bk + ob, nullptr, k, M, D_DIM, D_DIM, 0);
        gemm_kernel<<<grid_d, gemm_block>>>(x, Wv + od, bv + ob, nullptr, v, M, D_DIM, D_DIM, 0);

        attn_kernel<<<dim3(S_TOK, HEADS), 256>>>(q, k, v, ao);

        gemm_kernel<<<grid_d, gemm_block>>>(ao, Wo + od, bo + ob, x, tmp, M, D_DIM, D_DIM, 0);
        ln_kernel<<<S_TOK, 256>>>(tmp, ln1_g + ob, ln1_b + ob, x);

        gemm_kernel<<<grid_h, gemm_block>>>(x, W1 + o1w, b1 + o1b, nullptr, ffn, M, HID, D_DIM, 1);
        gemm_kernel<<<grid_d, gemm_block>>>(ffn, W2 + o1w, b2 + ob, x, tmp, M, D_DIM, HID, 0);
        ln_kernel<<<S_TOK, 256>>>(tmp, ln2_g + ob, ln2_b + ob, x);
    }

    // --- heads (node 0) -> d_out = [output(512) | new_concept(128)] ---
    float* out = (float*)d_out;
    matvec_kernel<<<OUT_N / 8, 256>>>(W_out, b_out, x, out, OUT_N, D_DIM, 1);
    matvec_kernel<<<CSZ / 8, 256>>>(W_concept, b_concept, x, out + OUT_N, CSZ, D_DIM, 2);

    (void)in_sizes; (void)n_in; (void)out_size;
}

// round 2
// speedup vs baseline: 1.6255x; 1.6255x over previous
#include <cuda_runtime.h>
#include <math.h>

#define S_TOK 257
#define D_DIM 1024
#define HID 4096
#define NLAYER 12
#define NC 256
#define CSZ 128
#define AGE_V 258
#define OBS_N 2048
#define OUT_N 512
#define HEADS 16
#define DH 64

// ---------------- scratch (device globals; no allocation allowed) ----------
__device__ float g_x[S_TOK * D_DIM];
__device__ float g_q[S_TOK * D_DIM];
__device__ float g_k[S_TOK * D_DIM];
__device__ float g_v[S_TOK * D_DIM];
__device__ float g_ao[S_TOK * D_DIM];
__device__ float g_tmp[S_TOK * D_DIM];
__device__ float g_ffn[S_TOK * HID];
__device__ float g_part[4 * S_TOK * D_DIM];   // split-K partials (KS<=4)

// ---------------- warp reduce helpers --------------------------------------
__device__ __forceinline__ float warpMax(float v) {
#pragma unroll
    for (int o = 16; o; o >>= 1) v = fmaxf(v, __shfl_xor_sync(0xffffffffu, v, o));
    return v;
}
__device__ __forceinline__ float warpSum(float v) {
#pragma unroll
    for (int o = 16; o; o >>= 1) v += __shfl_xor_sync(0xffffffffu, v, o);
    return v;
}

// ============================================================================
// GEMM core: C[M,N] = A[M,K] @ B[N,K]^T, BM=128, BN=64, BK=16, 256 threads,
// 8x4 micro-tile, double-buffered smem with register-staged global prefetch.
// ============================================================================
#define GBK 16

__device__ __forceinline__ void gemm128_core(
    const float* __restrict__ A, const float* __restrict__ B,
    int M, int K, int bm, int bn, int kbeg, int ktiles,
    float (&acc)[8][4],
    float (*As)[GBK][132], float (*Bs)[GBK][68])
{
    const int tid  = threadIdx.x;
    const int arow = tid >> 2;          // 0..63
    const int kq   = (tid & 3) << 2;    // 0,4,8,12
    const int tm   = tid >> 4;          // 0..15  (row group of 8)
    const int tn   = tid & 15;          // 0..15  (col group of 4)

    const int g0 = bm + arow;
    const int g1 = bm + arow + 64;
    const float* Arow0 = A + (size_t)g0 * K + kq;
    const float* Arow1 = A + (size_t)g1 * K + kq;
    const float* Brow  = B + (size_t)(bn + arow) * K + kq;

    float4 a0, a1, b0;
    // prologue: tile 0
    {
        const int kb = kbeg;
        a0 = (g0 < M) ? *(const float4*)(Arow0 + kb) : make_float4(0.f, 0.f, 0.f, 0.f);
        a1 = (g1 < M) ? *(const float4*)(Arow1 + kb) : make_float4(0.f, 0.f, 0.f, 0.f);
        b0 = *(const float4*)(Brow + kb);
    }
    int buf = 0;
    As[0][kq + 0][arow] = a0.x; As[0][kq + 1][arow] = a0.y;
    As[0][kq + 2][arow] = a0.z; As[0][kq + 3][arow] = a0.w;
    As[0][kq + 0][arow + 64] = a1.x; As[0][kq + 1][arow + 64] = a1.y;
    As[0][kq + 2][arow + 64] = a1.z; As[0][kq + 3][arow + 64] = a1.w;
    Bs[0][kq + 0][arow] = b0.x; Bs[0][kq + 1][arow] = b0.y;
    Bs[0][kq + 2][arow] = b0.z; Bs[0][kq + 3][arow] = b0.w;
    __syncthreads();

    for (int kt = 0; kt < ktiles; kt++) {
        float4 na0, na1, nb0;
        const bool has_next = (kt + 1 < ktiles);
        if (has_next) {
            const int kb = kbeg + (kt + 1) * GBK;
            na0 = (g0 < M) ? *(const float4*)(Arow0 + kb) : make_float4(0.f, 0.f, 0.f, 0.f);
            na1 = (g1 < M) ? *(const float4*)(Arow1 + kb) : make_float4(0.f, 0.f, 0.f, 0.f);
            nb0 = *(const float4*)(Brow + kb);
        }
#pragma unroll
        for (int kk = 0; kk < GBK; kk++) {
            const float4 va0 = *(const float4*)&As[buf][kk][tm * 8];
            const float4 va1 = *(const float4*)&As[buf][kk][tm * 8 + 4];
            const float4 vb  = *(const float4*)&Bs[buf][kk][tn * 4];
            const float am[8] = {va0.x, va0.y, va0.z, va0.w, va1.x, va1.y, va1.z, va1.w};
            const float bv[4] = {vb.x, vb.y, vb.z, vb.w};
#pragma unroll
            for (int i = 0; i < 8; i++)
#pragma unroll
                for (int j = 0; j < 4; j++)
                    acc[i][j] = fmaf(am[i], bv[j], acc[i][j]);
        }
        if (has_next) {
            const int nb = buf ^ 1;
            As[nb][kq + 0][arow] = na0.x; As[nb][kq + 1][arow] = na0.y;
            As[nb][kq + 2][arow] = na0.z; As[nb][kq + 3][arow] = na0.w;
            As[nb][kq + 0][arow + 64] = na1.x; As[nb][kq + 1][arow + 64] = na1.y;
            As[nb][kq + 2][arow + 64] = na1.z; As[nb][kq + 3][arow + 64] = na1.w;
            Bs[nb][kq + 0][arow] = nb0.x; Bs[nb][kq + 1][arow] = nb0.y;
            Bs[nb][kq + 2][arow] = nb0.z; Bs[nb][kq + 3][arow] = nb0.w;
            __syncthreads();
            buf = nb;
        }
    }
}

// ---- fused QKV: blockIdx.z selects which projection --------------------------
__global__ __launch_bounds__(256) void gemm_qkv_kernel(
    const float* __restrict__ A,
    const float* __restrict__ Wq_, const float* __restrict__ Wk_, const float* __restrict__ Wv_,
    const float* __restrict__ bq_, const float* __restrict__ bk_, const float* __restrict__ bv_,
    float* __restrict__ Q, float* __restrict__ Ko, float* __restrict__ V,
    int M, int N, int K)
{
    __shared__ float As[2][GBK][132];
    __shared__ float Bs[2][GBK][68];
    const int z = blockIdx.z;
    const float* B    = (z == 0) ? Wq_ : (z == 1) ? Wk_ : Wv_;
    const float* bias = (z == 0) ? bq_ : (z == 1) ? bk_ : bv_;
    float* C          = (z == 0) ? Q   : (z == 1) ? Ko  : V;

    const int bm = blockIdx.y * 128;
    const int bn = blockIdx.x * 64;
    float acc[8][4] = {};
    gemm128_core(A, B, M, K, bm, bn, 0, K / GBK, acc, As, Bs);

    const int tm = threadIdx.x >> 4, tn = threadIdx.x & 15;
    const float4 b4 = *(const float4*)(bias + bn + tn * 4);
#pragma unroll
    for (int i = 0; i < 8; i++) {
        const int gm = bm + tm * 8 + i;
        if (gm < M) {
            float4 o;
            o.x = acc[i][0] + b4.x; o.y = acc[i][1] + b4.y;
            o.z = acc[i][2] + b4.z; o.w = acc[i][3] + b4.w;
            *(float4*)(C + (size_t)gm * N + bn + tn * 4) = o;
        }
    }
}

// ---- direct GEMM with bias (+relu) ------------------------------------------
__global__ __launch_bounds__(256) void gemm_direct_kernel(
    const float* __restrict__ A, const float* __restrict__ B,
    const float* __restrict__ bias, float* __restrict__ C,
    int M, int N, int K, int relu_flag)
{
    __shared__ float As[2][GBK][132];
    __shared__ float Bs[2][GBK][68];
    const int bm = blockIdx.y * 128;
    const int bn = blockIdx.x * 64;
    float acc[8][4] = {};
    gemm128_core(A, B, M, K, bm, bn, 0, K / GBK, acc, As, Bs);

    const int tm = threadIdx.x >> 4, tn = threadIdx.x & 15;
    const float4 b4 = *(const float4*)(bias + bn + tn * 4);
#pragma unroll
    for (int i = 0; i < 8; i++) {
        const int gm = bm + tm * 8 + i;
        if (gm < M) {
            float4 o;
            o.x = acc[i][0] + b4.x; o.y = acc[i][1] + b4.y;
            o.z = acc[i][2] + b4.z; o.w = acc[i][3] + b4.w;
            if (relu_flag) {
                o.x = fmaxf(o.x, 0.f); o.y = fmaxf(o.y, 0.f);
                o.z = fmaxf(o.z, 0.f); o.w = fmaxf(o.w, 0.f);
            }
            *(float4*)(C + (size_t)gm * N + bn + tn * 4) = o;
        }
    }
}

// ---- split-K GEMM: writes partials, no bias ---------------------------------
__global__ __launch_bounds__(256) void gemm_splitk_kernel(
    const float* __restrict__ A, const float* __restrict__ B,
    float* __restrict__ part, int M, int N, int K, int Ksplit)
{
    __shared__ float As[2][GBK][132];
    __shared__ float Bs[2][GBK][68];
    const int bm = blockIdx.y * 128;
    const int bn = blockIdx.x * 64;
    const int z  = blockIdx.z;
    float acc[8][4] = {};
    gemm128_core(A, B, M, K, bm, bn, z * Ksplit, Ksplit / GBK, acc, As, Bs);

    const int tm = threadIdx.x >> 4, tn = threadIdx.x & 15;
#pragma unroll
    for (int i = 0; i < 8; i++) {
        const int gm = bm + tm * 8 + i;
        if (gm < M) {
            float4 o;
            o.x = acc[i][0]; o.y = acc[i][1]; o.z = acc[i][2]; o.w = acc[i][3];
            *(float4*)(part + ((size_t)z * M + gm) * N + bn + tn * 4) = o;
        }
    }
}

// ---- combine split-K partials + bias + residual (+relu) ---------------------
__global__ __launch_bounds__(256) void combine_kernel(
    const float* __restrict__ part, int KS,
    const float* __restrict__ bias, const float* __restrict__ res,
    float* __restrict__ out, int M, int N, int act)
{
    const int idx = blockIdx.x * 256 + threadIdx.x;   // float4 index
    const int n4 = N >> 2;
    const int total = M * n4;
    if (idx >= total) return;
    const int row = idx / n4;
    const int c4  = idx - row * n4;
    const float4* p = (const float4*)part;
    float4 s = p[(size_t)row * n4 + c4];
    for (int z = 1; z < KS; z++) {
        const float4 t = p[((size_t)z * M + row) * n4 + c4];
        s.x += t.x; s.y += t.y; s.z += t.z; s.w += t.w;
    }
    const float4 b = ((const float4*)bias)[c4];
    s.x += b.x; s.y += b.y; s.z += b.z; s.w += b.w;
    if (res) {
        const float4 r = ((const float4*)res)[(size_t)row * n4 + c4];
        s.x += r.x; s.y += r.y; s.z += r.z; s.w += r.w;
    }
    if (act == 1) {
        s.x = fmaxf(s.x, 0.f); s.y = fmaxf(s.y, 0.f);
        s.z = fmaxf(s.z, 0.f); s.w = fmaxf(s.w, 0.f);
    }
    ((float4*)out)[(size_t)row * n4 + c4] = s;
}

// ---------------- matvec: out[n] = act(dot(W[n,:], x) + bias[n]) -----------
__global__ __launch_bounds__(256) void matvec_kernel(
    const float* __restrict__ W, const float* __restrict__ bias,
    const float* __restrict__ x, float* __restrict__ out,
    int N, int K, int act)
{
    __shared__ float xs[OBS_N];
    const int tid = threadIdx.x;
    for (int i = tid; i < K; i += 256) xs[i] = x[i];
    __syncthreads();
    const int warp = tid >> 5, lane = tid & 31;
    const int n = blockIdx.x * 8 + warp;
    if (n >= N) return;
    const float4* wr = reinterpret_cast<const float4*>(W + (size_t)n * K);
    const float4* x4 = reinterpret_cast<const float4*>(xs);
    float s = 0.f;
    const int K4 = K >> 2;
    for (int kb = lane; kb < K4; kb += 32) {
        float4 w = wr[kb], xv = x4[kb];
        s += w.x * xv.x + w.y * xv.y + w.z * xv.z + w.w * xv.w;
    }
    s = warpSum(s);
    if (lane == 0) {
        s += bias[n];
        if (act == 1) s = fmaxf(s, 0.f);
        else if (act == 2) s = tanhf(s);
        out[n] = s;
    }
}

// ---------------- concept embedding (rows 1..256 of x) ---------------------
__global__ __launch_bounds__(256) void cemb_kernel(
    const float* __restrict__ concepts, const float* __restrict__ Wc,
    const float* __restrict__ bc, const float* __restrict__ Wage,
    const float* __restrict__ bage, float* __restrict__ x)
{
    const int i = blockIdx.x;
    const int tid = threadIdx.x;
    __shared__ float cv[CSZ];
    if (tid < CSZ) cv[tid] = concepts[i * CSZ + tid];
    __syncthreads();
    const float agef = (float)i / 256.0f;
    for (int d = tid; d < D_DIM; d += 256) {
        const float4* wr = reinterpret_cast<const float4*>(Wc + (size_t)d * CSZ);
        const float4* c4 = reinterpret_cast<const float4*>(cv);
        float s = 0.f;
#pragma unroll
        for (int t = 0; t < CSZ / 4; t++) {
            float4 w = wr[t], c = c4[t];
            s += w.x * c.x + w.y * c.y + w.z * c.z + w.w * c.w;
        }
        s += bc[d] + Wage[(size_t)d * AGE_V + i] + agef * Wage[(size_t)d * AGE_V + (AGE_V - 1)] + bage[d];
        x[(size_t)(i + 1) * D_DIM + d] = s;
    }
}

// ---------------- attention: one block per (query, head) -------------------
__global__ __launch_bounds__(256) void attn_kernel(
    const float* __restrict__ q, const float* __restrict__ k,
    const float* __restrict__ v, float* __restrict__ o)
{
    const int qi = blockIdx.x;
    const int h = blockIdx.y;
    const int tid = threadIdx.x;
    const int lane = tid & 31, warp = tid >> 5;

    __shared__ float qv[DH];
    __shared__ float sc[S_TOK];
    __shared__ float red[8];
    __shared__ float part[256];
    __shared__ float s_max, s_sum;

    if (tid < DH) qv[tid] = q[(size_t)qi * D_DIM + h * DH + tid];
    __syncthreads();

    float lmax = -1e30f;
    for (int j = tid; j < S_TOK; j += 256) {
        const float4* kr = reinterpret_cast<const float4*>(k + (size_t)j * D_DIM + h * DH);
        const float4* q4 = reinterpret_cast<const float4*>(qv);
        float s = 0.f;
#pragma unroll
        for (int t = 0; t < DH / 4; t++) {
            float4 kv = kr[t], qq = q4[t];
            s += kv.x * qq.x + kv.y * qq.y + kv.z * qq.z + kv.w * qq.w;
        }
        s *= 0.125f;
        sc[j] = s;
        lmax = fmaxf(lmax, s);
    }
    lmax = warpMax(lmax);
    if (lane == 0) red[warp] = lmax;
    __syncthreads();
    if (warp == 0) {
        float t = (lane < 8) ? red[lane] : -1e30f;
        t = warpMax(t);
        if (lane == 0) s_max = t;
    }
    __syncthreads();
    const float mx = s_max;

    float lsum = 0.f;
    for (int j = tid; j < S_TOK; j += 256) {
        float e = __expf(sc[j] - mx);
        sc[j] = e;
        lsum += e;
    }
    lsum = warpSum(lsum);
    __syncthreads();
    if (lane == 0) red[warp] = lsum;
    __syncthreads();
    if (warp == 0) {
        float t = (lane < 8) ? red[lane] : 0.f;
        t = warpSum(t);
        if (lane == 0) s_sum = t;
    }
    __syncthreads();
    const float inv_sum = 1.0f / s_sum;

    const int d = tid & 63, jg = tid >> 6;
    float acc = 0.f;
    for (int j = jg; j < S_TOK; j += 4)
        acc = fmaf(sc[j], v[(size_t)j * D_DIM + h * DH + d], acc);
    part[tid] = acc;
    __syncthreads();
    if (tid < DH) {
        float r = (part[tid] + part[64 + tid] + part[128 + tid] + part[192 + tid]) * inv_sum;
        o[(size_t)qi * D_DIM + h * DH + tid] = r;
    }
}

// ---------------- layernorm over rows --------------------------------------
__global__ __launch_bounds__(256) void ln_kernel(
    const float* __restrict__ in, const float* __restrict__ g,
    const float* __restrict__ b, float* __restrict__ out)
{
    const int r = blockIdx.x;
    const int tid = threadIdx.x;
    const int lane = tid & 31, warp = tid >> 5;
    __shared__ float rs[8], rs2[8];

    const float4 v4 = reinterpret_cast<const float4*>(in + (size_t)r * D_DIM)[tid];
    float s = v4.x + v4.y + v4.z + v4.w;
    float s2 = v4.x * v4.x + v4.y * v4.y + v4.z * v4.z + v4.w * v4.w;
    s = warpSum(s); s2 = warpSum(s2);
    if (lane == 0) { rs[warp] = s; rs2[warp] = s2; }
    __syncthreads();
    __shared__ float sm, sv;
    if (warp == 0) {
        float t = (lane < 8) ? rs[lane] : 0.f;
        float t2 = (lane < 8) ? rs2[lane] : 0.f;
        t = warpSum(t); t2 = warpSum(t2);
        if (lane == 0) {
            float mean = t * (1.0f / D_DIM);
            float var = t2 * (1.0f / D_DIM) - mean * mean;
            sm = mean;
            sv = rsqrtf(var + 1e-5f);
        }
    }
    __syncthreads();
    const float mean = sm, inv = sv;
    const float4 g4 = reinterpret_cast<const float4*>(g)[tid];
    const float4 b4 = reinterpret_cast<const float4*>(b)[tid];
    float4 o;
    o.x = (v4.x - mean) * inv * g4.x + b4.x;
    o.y = (v4.y - mean) * inv * g4.y + b4.y;
    o.z = (v4.z - mean) * inv * g4.z + b4.z;
    o.w = (v4.w - mean) * inv * g4.w + b4.w;
    reinterpret_cast<float4*>(out + (size_t)r * D_DIM)[tid] = o;
}

// ---------------- host launch ----------------------------------------------
extern "C" void kernel_launch(void* const* d_in, const int* in_sizes, int n_in,
                              void* d_out, int out_size)
{
    const float* observation = (const float*)d_in[0];
    const float* concepts    = (const float*)d_in[1];
    const float* W_core = (const float*)d_in[2];
    const float* b_core = (const float*)d_in[3];
    const float* W_cemb = (const float*)d_in[4];
    const float* b_cemb = (const float*)d_in[5];
    const float* W_age  = (const float*)d_in[6];
    const float* b_age  = (const float*)d_in[7];
    const float* Wq = (const float*)d_in[8];
    const float* bq = (const float*)d_in[9];
    const float* Wk = (const float*)d_in[10];
    const float* bk = (const float*)d_in[11];
    const float* Wv = (const float*)d_in[12];
    const float* bv = (const float*)d_in[13];
    const float* Wo = (const float*)d_in[14];
    const float* bo = (const float*)d_in[15];
    const float* ln1_g = (const float*)d_in[16];
    const float* ln1_b = (const float*)d_in[17];
    const float* W1 = (const float*)d_in[18];
    const float* b1 = (const float*)d_in[19];
    const float* W2 = (const float*)d_in[20];
    const float* b2 = (const float*)d_in[21];
    const float* ln2_g = (const float*)d_in[22];
    const float* ln2_b = (const float*)d_in[23];
    const float* W_concept = (const float*)d_in[24];
    const float* b_concept = (const float*)d_in[25];
    const float* W_out = (const float*)d_in[26];
    const float* b_out = (const float*)d_in[27];

    float *x, *q, *k, *v, *ao, *tmp, *ffn, *part;
    cudaGetSymbolAddress((void**)&x, g_x);
    cudaGetSymbolAddress((void**)&q, g_q);
    cudaGetSymbolAddress((void**)&k, g_k);
    cudaGetSymbolAddress((void**)&v, g_v);
    cudaGetSymbolAddress((void**)&ao, g_ao);
    cudaGetSymbolAddress((void**)&tmp, g_tmp);
    cudaGetSymbolAddress((void**)&ffn, g_ffn);
    cudaGetSymbolAddress((void**)&part, g_part);

    const int M = S_TOK;
    const dim3 blk(256);
    const dim3 grid_qkv(D_DIM / 64, 3, 3);      // 16 x 3 x 3 = 144 blocks
    const dim3 grid_w1(HID / 64, 3);            // 64 x 3 = 192 blocks
    const dim3 grid_skD(D_DIM / 64, 3, 4);      // 16 x 3 x 4 = 192 blocks
    const int comb_blocks = (M * (D_DIM / 4) + 255) / 256;   // 257

    // --- embeddings ---
    matvec_kernel<<<D_DIM / 8, 256>>>(W_core, b_core, observation, x, D_DIM, OBS_N, 0);
    cemb_kernel<<<NC, 256>>>(concepts, W_cemb, b_cemb, W_age, b_age, x);

    // --- transformer layers ---
    for (int l = 0; l < NLAYER; l++) {
        const size_t od  = (size_t)l * D_DIM * D_DIM;
        const size_t ob  = (size_t)l * D_DIM;
        const size_t o1w = (size_t)l * HID * D_DIM;
        const size_t o1b = (size_t)l * HID;

        gemm_qkv_kernel<<<grid_qkv, blk>>>(x, Wq + od, Wk + od, Wv + od,
                                           bq + ob, bk + ob, bv + ob,
                                           q, k, v, M, D_DIM, D_DIM);

        attn_kernel<<<dim3(S_TOK, HEADS), 256>>>(q, k, v, ao);

        gemm_splitk_kernel<<<grid_skD, blk>>>(ao, Wo + od, part, M, D_DIM, D_DIM, D_DIM / 4);
        combine_kernel<<<comb_blocks, 256>>>(part, 4, bo + ob, x, tmp, M, D_DIM, 0);
        ln_kernel<<<S_TOK, 256>>>(tmp, ln1_g + ob, ln1_b + ob, x);

        gemm_direct_kernel<<<grid_w1, blk>>>(x, W1 + o1w, b1 + o1b, ffn, M, HID, D_DIM, 1);
        gemm_splitk_kernel<<<grid_skD, blk>>>(ffn, W2 + o1w, part, M, D_DIM, HID, HID / 4);
        combine_kernel<<<comb_blocks, 256>>>(part, 4, b2 + ob, x, tmp, M, D_DIM, 0);
        ln_kernel<<<S_TOK, 256>>>(tmp, ln2_g + ob, ln2_b + ob, x);
    }

    // --- heads (node 0) -> d_out = [output(512) | new_concept(128)] ---
    float* out = (float*)d_out;
    matvec_kernel<<<OUT_N / 8, 256>>>(W_out, b_out, x, out, OUT_N, D_DIM, 1);
    matvec_kernel<<<CSZ / 8, 256>>>(W_concept, b_concept, x, out + OUT_N, CSZ, D_DIM, 2);

    (void)in_sizes; (void)n_in; (void)out_size;
}

// round 3
// speedup vs baseline: 4.7911x; 2.9475x over previous
#include <cuda_runtime.h>
#include <math.h>
#include <stdint.h>

#define S_TOK 257
#define D_DIM 1024
#define HID 4096
#define NLAYER 12
#define NC 256
#define CSZ 128
#define AGE_V 258
#define OBS_N 2048
#define OUT_N 512
#define HEADS 16
#define DH 64

// ---------------- scratch (device globals; no allocation allowed) ----------
__device__ float g_x[S_TOK * D_DIM];
__device__ float g_q[S_TOK * D_DIM];
__device__ float g_k[S_TOK * D_DIM];
__device__ float g_v[S_TOK * D_DIM];
__device__ float g_ao[S_TOK * D_DIM];
__device__ float g_ffn[S_TOK * HID];
__device__ float g_part[4 * S_TOK * D_DIM];   // split-K partials (KS<=4)

// ---------------- helpers ---------------------------------------------------
__device__ __forceinline__ float warpMax(float v) {
#pragma unroll
    for (int o = 16; o; o >>= 1) v = fmaxf(v, __shfl_xor_sync(0xffffffffu, v, o));
    return v;
}
__device__ __forceinline__ float warpSum(float v) {
#pragma unroll
    for (int o = 16; o; o >>= 1) v += __shfl_xor_sync(0xffffffffu, v, o);
    return v;
}
__device__ __forceinline__ uint32_t f2tf(float f) {
    uint32_t u;
    asm("cvt.rna.tf32.f32 %0, %1;" : "=r"(u) : "f"(f));
    return u;
}
__device__ __forceinline__ void mma1688(float (&d)[4], const uint32_t (&a)[4], const uint32_t (&b)[2]) {
    asm volatile(
        "mma.sync.aligned.m16n8k8.row.col.f32.tf32.tf32.f32 "
        "{%0,%1,%2,%3}, {%4,%5,%6,%7}, {%8,%9}, {%0,%1,%2,%3};\n"
        : "+f"(d[0]), "+f"(d[1]), "+f"(d[2]), "+f"(d[3])
        : "r"(a[0]), "r"(a[1]), "r"(a[2]), "r"(a[3]), "r"(b[0]), "r"(b[1]));
}

// ============================================================================
// tf32 GEMM core: C[M,N] = A[M,K] @ B[N,K]^T. Block 64x64, BK=32, 256 threads
// (8 warps, 2x4 warp grid, each warp 32x16 via 2x2 m16n8k8 tiles).
// Smem stride 36 -> conflict-free fragment loads. Register-staged prefetch.
// ============================================================================
__device__ __forceinline__ void tf32_core(
    const float* __restrict__ A, const float* __restrict__ B,
    int M, int K, int bm, int bn, int kbeg, int ktiles,
    float (&acc)[2][2][4], uint32_t (*As)[36], uint32_t (*Bs)[36])
{
    const int tid = threadIdx.x;
    const int lane = tid & 31, wid = tid >> 5;
    const int wm = wid & 1, wn = wid >> 1;
    const int fr = lane >> 2, fc = lane & 3;

    int arow[2], akq[2];
    bool aval[2];
    const float* aptr[2];
    const float* bptr[2];
#pragma unroll
    for (int i = 0; i < 2; i++) {
        const int idx = tid + i * 256;
        const int row = idx >> 3, kq = (idx & 7) << 2;
        arow[i] = row; akq[i] = kq;
        aval[i] = (bm + row) < M;
        aptr[i] = A + (size_t)(bm + row) * K + kbeg + kq;
        bptr[i] = B + (size_t)(bn + row) * K + kbeg + kq;
    }

    float4 pa[2], pb[2];
#pragma unroll
    for (int i = 0; i < 2; i++) {
        pa[i] = aval[i] ? *(const float4*)(aptr[i]) : make_float4(0.f, 0.f, 0.f, 0.f);
        pb[i] = *(const float4*)(bptr[i]);
    }
#pragma unroll
    for (int i = 0; i < 2; i++) {
        *(uint4*)&As[arow[i]][akq[i]] = make_uint4(f2tf(pa[i].x), f2tf(pa[i].y), f2tf(pa[i].z), f2tf(pa[i].w));
        *(uint4*)&Bs[arow[i]][akq[i]] = make_uint4(f2tf(pb[i].x), f2tf(pb[i].y), f2tf(pb[i].z), f2tf(pb[i].w));
    }
    __syncthreads();

    for (int kt = 0; kt < ktiles; kt++) {
        const bool has_next = (kt + 1 < ktiles);
        if (has_next) {
            const int off = (kt + 1) * 32;
#pragma unroll
            for (int i = 0; i < 2; i++) {
                pa[i] = aval[i] ? *(const float4*)(aptr[i] + off) : make_float4(0.f, 0.f, 0.f, 0.f);
                pb[i] = *(const float4*)(bptr[i] + off);
            }
        }
#pragma unroll
        for (int k0 = 0; k0 < 32; k0 += 8) {
            uint32_t af[2][4], bf[2][2];
#pragma unroll
            for (int mi = 0; mi < 2; mi++) {
                const int r = wm * 32 + mi * 16 + fr;
                af[mi][0] = As[r][k0 + fc];
                af[mi][1] = As[r + 8][k0 + fc];
                af[mi][2] = As[r][k0 + fc + 4];
                af[mi][3] = As[r + 8][k0 + fc + 4];
            }
#pragma unroll
            for (int ni = 0; ni < 2; ni++) {
                const int c = wn * 16 + ni * 8 + fr;
                bf[ni][0] = Bs[c][k0 + fc];
                bf[ni][1] = Bs[c][k0 + fc + 4];
            }
#pragma unroll
            for (int mi = 0; mi < 2; mi++)
#pragma unroll
                for (int ni = 0; ni < 2; ni++)
                    mma1688(acc[mi][ni], af[mi], bf[ni]);
        }
        if (has_next) {
            __syncthreads();
#pragma unroll
            for (int i = 0; i < 2; i++) {
                *(uint4*)&As[arow[i]][akq[i]] = make_uint4(f2tf(pa[i].x), f2tf(pa[i].y), f2tf(pa[i].z), f2tf(pa[i].w));
                *(uint4*)&Bs[arow[i]][akq[i]] = make_uint4(f2tf(pb[i].x), f2tf(pb[i].y), f2tf(pb[i].z), f2tf(pb[i].w));
            }
            __syncthreads();
        }
    }
}

// ---- fused QKV ---------------------------------------------------------------
__global__ __launch_bounds__(256) void gemm_qkv_kernel(
    const float* __restrict__ A,
    const float* __restrict__ Wq_, const float* __restrict__ Wk_, const float* __restrict__ Wv_,
    const float* __restrict__ bq_, const float* __restrict__ bk_, const float* __restrict__ bv_,
    float* __restrict__ Q, float* __restrict__ Ko, float* __restrict__ V,
    int M, int N, int K)
{
    __shared__ uint32_t As[64][36];
    __shared__ uint32_t Bs[64][36];
    const int z = blockIdx.z;
    const float* B    = (z == 0) ? Wq_ : (z == 1) ? Wk_ : Wv_;
    const float* bias = (z == 0) ? bq_ : (z == 1) ? bk_ : bv_;
    float* C          = (z == 0) ? Q   : (z == 1) ? Ko  : V;

    const int bm = blockIdx.y * 64;
    const int bn = blockIdx.x * 64;
    float acc[2][2][4] = {};
    tf32_core(A, B, M, K, bm, bn, 0, K / 32, acc, As, Bs);

    const int lane = threadIdx.x & 31, wid = threadIdx.x >> 5;
    const int wm = wid & 1, wn = wid >> 1;
    const int fr = lane >> 2, fc = lane & 3;
#pragma unroll
    for (int mi = 0; mi < 2; mi++)
#pragma unroll
        for (int ni = 0; ni < 2; ni++) {
            const int r = bm + wm * 32 + mi * 16 + fr;
            const int c = bn + wn * 16 + ni * 8 + fc * 2;
            const float bx = bias[c], by = bias[c + 1];
            if (r < M) {
                float2 o = {acc[mi][ni][0] + bx, acc[mi][ni][1] + by};
                *(float2*)(C + (size_t)r * N + c) = o;
            }
            if (r + 8 < M) {
                float2 o = {acc[mi][ni][2] + bx, acc[mi][ni][3] + by};
                *(float2*)(C + (size_t)(r + 8) * N + c) = o;
            }
        }
}

// ---- direct GEMM with bias (+relu) -------------------------------------------
__global__ __launch_bounds__(256) void gemm_direct_kernel(
    const float* __restrict__ A, const float* __restrict__ B,
    const float* __restrict__ bias, float* __restrict__ C,
    int M, int N, int K, int relu_flag)
{
    __shared__ uint32_t As[64][36];
    __shared__ uint32_t Bs[64][36];
    const int bm = blockIdx.y * 64;
    const int bn = blockIdx.x * 64;
    float acc[2][2][4] = {};
    tf32_core(A, B, M, K, bm, bn, 0, K / 32, acc, As, Bs);

    const int lane = threadIdx.x & 31, wid = threadIdx.x >> 5;
    const int wm = wid & 1, wn = wid >> 1;
    const int fr = lane >> 2, fc = lane & 3;
#pragma unroll
    for (int mi = 0; mi < 2; mi++)
#pragma unroll
        for (int ni = 0; ni < 2; ni++) {
            const int r = bm + wm * 32 + mi * 16 + fr;
            const int c = bn + wn * 16 + ni * 8 + fc * 2;
            const float bx = bias[c], by = bias[c + 1];
            if (r < M) {
                float2 o = {acc[mi][ni][0] + bx, acc[mi][ni][1] + by};
                if (relu_flag) { o.x = fmaxf(o.x, 0.f); o.y = fmaxf(o.y, 0.f); }
                *(float2*)(C + (size_t)r * N + c) = o;
            }
            if (r + 8 < M) {
                float2 o = {acc[mi][ni][2] + bx, acc[mi][ni][3] + by};
                if (relu_flag) { o.x = fmaxf(o.x, 0.f); o.y = fmaxf(o.y, 0.f); }
                *(float2*)(C + (size_t)(r + 8) * N + c) = o;
            }
        }
}

// ---- split-K GEMM (raw partials) ---------------------------------------------
__global__ __launch_bounds__(256) void gemm_splitk_kernel(
    const float* __restrict__ A, const float* __restrict__ B,
    float* __restrict__ part, int M, int N, int K, int klen)
{
    __shared__ uint32_t As[64][36];
    __shared__ uint32_t Bs[64][36];
    const int bm = blockIdx.y * 64;
    const int bn = blockIdx.x * 64;
    const int z = blockIdx.z;
    float acc[2][2][4] = {};
    tf32_core(A, B, M, K, bm, bn, z * klen, klen / 32, acc, As, Bs);

    float* C = part + (size_t)z * M * N;
    const int lane = threadIdx.x & 31, wid = threadIdx.x >> 5;
    const int wm = wid & 1, wn = wid >> 1;
    const int fr = lane >> 2, fc = lane & 3;
#pragma unroll
    for (int mi = 0; mi < 2; mi++)
#pragma unroll
        for (int ni = 0; ni < 2; ni++) {
            const int r = bm + wm * 32 + mi * 16 + fr;
            const int c = bn + wn * 16 + ni * 8 + fc * 2;
            if (r < M) {
                float2 o = {acc[mi][ni][0], acc[mi][ni][1]};
                *(float2*)(C + (size_t)r * N + c) = o;
            }
            if (r + 8 < M) {
                float2 o = {acc[mi][ni][2], acc[mi][ni][3]};
                *(float2*)(C + (size_t)(r + 8) * N + c) = o;
            }
        }
}

// ---- fused combine(split-K) + bias + residual + LayerNorm --------------------
// one block per row, N = D_DIM = 1024, 256 threads (1 float4 each)
__global__ __launch_bounds__(256) void combine_ln_kernel(
    const float* __restrict__ part, int KS,
    const float* __restrict__ bias, const float* __restrict__ res,
    const float* __restrict__ g, const float* __restrict__ b,
    float* __restrict__ out, int M)
{
    const int row = blockIdx.x;
    const int tid = threadIdx.x;
    const int lane = tid & 31, warp = tid >> 5;
    __shared__ float rs[8], rs2[8];
    __shared__ float smv[2];

    float4 s = ((const float4*)(part + (size_t)row * D_DIM))[tid];
    for (int z = 1; z < KS; z++) {
        const float4 t = ((const float4*)(part + ((size_t)z * M + row) * D_DIM))[tid];
        s.x += t.x; s.y += t.y; s.z += t.z; s.w += t.w;
    }
    const float4 b4 = ((const float4*)bias)[tid];
    s.x += b4.x; s.y += b4.y; s.z += b4.z; s.w += b4.w;
    const float4 r4 = ((const float4*)(res + (size_t)row * D_DIM))[tid];
    s.x += r4.x; s.y += r4.y; s.z += r4.z; s.w += r4.w;

    float sum = s.x + s.y + s.z + s.w;
    float sq = s.x * s.x + s.y * s.y + s.z * s.z + s.w * s.w;
    sum = warpSum(sum); sq = warpSum(sq);
    if (lane == 0) { rs[warp] = sum; rs2[warp] = sq; }
    __syncthreads();
    if (warp == 0) {
        float t = (lane < 8) ? rs[lane] : 0.f;
        float t2 = (lane < 8) ? rs2[lane] : 0.f;
        t = warpSum(t); t2 = warpSum(t2);
        if (lane == 0) {
            const float mean = t * (1.0f / D_DIM);
            const float var = t2 * (1.0f / D_DIM) - mean * mean;
            smv[0] = mean;
            smv[1] = rsqrtf(var + 1e-5f);
        }
    }
    __syncthreads();
    const float mean = smv[0], inv = smv[1];
    const float4 g4 = ((const float4*)g)[tid];
    const float4 be4 = ((const float4*)b)[tid];
    float4 o;
    o.x = (s.x - mean) * inv * g4.x + be4.x;
    o.y = (s.y - mean) * inv * g4.y + be4.y;
    o.z = (s.z - mean) * inv * g4.z + be4.z;
    o.w = (s.w - mean) * inv * g4.w + be4.w;
    ((float4*)(out + (size_t)row * D_DIM))[tid] = o;
}

// ---------------- attention: block per (head, 32-query tile) ----------------
__global__ __launch_bounds__(256) void attn2_kernel(
    const float* __restrict__ q, const float* __restrict__ k,
    const float* __restrict__ v, float* __restrict__ o)
{
    const int h = blockIdx.x;
    const int qt = blockIdx.y * 32;
    const int tid = threadIdx.x, lane = tid & 31, warp = tid >> 5;

    __shared__ float Qs[32][68];
    __shared__ float T[64][68];
    __shared__ float sc[32][261];
    __shared__ float inv_s[32];

    const int nq = min(32, S_TOK - qt);

    // load Q tile
#pragma unroll
    for (int i = 0; i < 2; i++) {
        const int idx = tid + i * 256;
        const int r = idx >> 4, c4 = (idx & 15) << 2;
        float4 val = (r < nq) ? *(const float4*)(q + (size_t)(qt + r) * D_DIM + h * DH + c4)
                              : make_float4(0.f, 0.f, 0.f, 0.f);
        *(float4*)&Qs[r][c4] = val;
    }

    const int qrow = tid & 31, jg = tid >> 5;

    // phase 1: scores
    for (int j0 = 0; j0 < S_TOK; j0 += 64) {
        const int jn = min(64, S_TOK - j0);
        __syncthreads();
#pragma unroll
        for (int i = 0; i < 4; i++) {
            const int idx = tid + i * 256;
            const int r = idx >> 4, c4 = (idx & 15) << 2;
            float4 val = (r < jn) ? *(const float4*)(k + (size_t)(j0 + r) * D_DIM + h * DH + c4)
                                  : make_float4(0.f, 0.f, 0.f, 0.f);
            *(float4*)&T[r][c4] = val;
        }
        __syncthreads();
        for (int jj = jg; jj < jn; jj += 8) {
            const float4* qr4 = (const float4*)Qs[qrow];
            const float4* kr4 = (const float4*)T[jj];
            float s = 0.f;
#pragma unroll
            for (int t = 0; t < 16; t++) {
                const float4 a = qr4[t], bb = kr4[t];
                s += a.x * bb.x + a.y * bb.y + a.z * bb.z + a.w * bb.w;
            }
            sc[qrow][j0 + jj] = s * 0.125f;
        }
    }
    __syncthreads();

    // phase 2: softmax (one warp -> 4 rows)
#pragma unroll
    for (int ri = 0; ri < 4; ri++) {
        const int r = warp * 4 + ri;
        if (r < nq) {
            float m = -1e30f;
            for (int j = lane; j < S_TOK; j += 32) m = fmaxf(m, sc[r][j]);
            m = warpMax(m);
            float ssum = 0.f;
            for (int j = lane; j < S_TOK; j += 32) {
                const float e = __expf(sc[r][j] - m);
                sc[r][j] = e;
                ssum += e;
            }
            ssum = warpSum(ssum);
            if (lane == 0) inv_s[r] = 1.0f / ssum;
        }
    }
    __syncthreads();

    // phase 3: attn @ V
    const int db = warp * 8;
    float4 acc0 = make_float4(0.f, 0.f, 0.f, 0.f);
    float4 acc1 = make_float4(0.f, 0.f, 0.f, 0.f);
    for (int j0 = 0; j0 < S_TOK; j0 += 64) {
        const int jn = min(64, S_TOK - j0);
        __syncthreads();
#pragma unroll
        for (int i = 0; i < 4; i++) {
            const int idx = tid + i * 256;
            const int r = idx >> 4, c4 = (idx & 15) << 2;
            float4 val = (r < jn) ? *(const float4*)(v + (size_t)(j0 + r) * D_DIM + h * DH + c4)
                                  : make_float4(0.f, 0.f, 0.f, 0.f);
            *(float4*)&T[r][c4] = val;
        }
        __syncthreads();
        for (int jj = 0; jj < jn; jj++) {
            const float w = sc[qrow][j0 + jj];
            const float4 v0 = *(const float4*)&T[jj][db];
            const float4 v1 = *(const float4*)&T[jj][db + 4];
            acc0.x += w * v0.x; acc0.y += w * v0.y; acc0.z += w * v0.z; acc0.w += w * v0.w;
            acc1.x += w * v1.x; acc1.y += w * v1.y; acc1.z += w * v1.z; acc1.w += w * v1.w;
        }
    }
    if (qrow < nq) {
        const float iv = inv_s[qrow];
        float* op = o + (size_t)(qt + qrow) * D_DIM + h * DH + db;
        float4 o0 = {acc0.x * iv, acc0.y * iv, acc0.z * iv, acc0.w * iv};
        float4 o1 = {acc1.x * iv, acc1.y * iv, acc1.z * iv, acc1.w * iv};
        *(float4*)(op) = o0;
        *(float4*)(op + 4) = o1;
    }
}

// ---------------- matvec (embeddings / heads) -------------------------------
__global__ __launch_bounds__(256) void matvec_kernel(
    const float* __restrict__ W, const float* __restrict__ bias,
    const float* __restrict__ x, float* __restrict__ out,
    int N, int K, int act)
{
    __shared__ float xs[OBS_N];
    const int tid = threadIdx.x;
    for (int i = tid; i < K; i += 256) xs[i] = x[i];
    __syncthreads();
    const int warp = tid >> 5, lane = tid & 31;
    const int n = blockIdx.x * 8 + warp;
    if (n >= N) return;
    const float4* wr = reinterpret_cast<const float4*>(W + (size_t)n * K);
    const float4* x4 = reinterpret_cast<const float4*>(xs);
    float s = 0.f;
    const int K4 = K >> 2;
    for (int kb = lane; kb < K4; kb += 32) {
        const float4 w = wr[kb], xv = x4[kb];
        s += w.x * xv.x + w.y * xv.y + w.z * xv.z + w.w * xv.w;
    }
    s = warpSum(s);
    if (lane == 0) {
        s += bias[n];
        if (act == 1) s = fmaxf(s, 0.f);
        else if (act == 2) s = tanhf(s);
        out[n] = s;
    }
}

// ---------------- concept embedding (rows 1..256 of x) ---------------------
__global__ __launch_bounds__(256) void cemb_kernel(
    const float* __restrict__ concepts, const float* __restrict__ Wc,
    const float* __restrict__ bc, const float* __restrict__ Wage,
    const float* __restrict__ bage, float* __restrict__ x)
{
    const int i = blockIdx.x;
    const int tid = threadIdx.x;
    __shared__ float cv[CSZ];
    if (tid < CSZ) cv[tid] = concepts[i * CSZ + tid];
    __syncthreads();
    const float agef = (float)i / 256.0f;
    for (int d = tid; d < D_DIM; d += 256) {
        const float4* wr = reinterpret_cast<const float4*>(Wc + (size_t)d * CSZ);
        const float4* c4 = reinterpret_cast<const float4*>(cv);
        float s = 0.f;
#pragma unroll
        for (int t = 0; t < CSZ / 4; t++) {
            const float4 w = wr[t], c = c4[t];
            s += w.x * c.x + w.y * c.y + w.z * c.z + w.w * c.w;
        }
        s += bc[d] + Wage[(size_t)d * AGE_V + i] + agef * Wage[(size_t)d * AGE_V + (AGE_V - 1)] + bage[d];
        x[(size_t)(i + 1) * D_DIM + d] = s;
    }
}

// ---------------- host launch ----------------------------------------------
extern "C" void kernel_launch(void* const* d_in, const int* in_sizes, int n_in,
                              void* d_out, int out_size)
{
    const float* observation = (const float*)d_in[0];
    const float* concepts    = (const float*)d_in[1];
    const float* W_core = (const float*)d_in[2];
    const float* b_core = (const float*)d_in[3];
    const float* W_cemb = (const float*)d_in[4];
    const float* b_cemb = (const float*)d_in[5];
    const float* W_age  = (const float*)d_in[6];
    const float* b_age  = (const float*)d_in[7];
    const float* Wq = (const float*)d_in[8];
    const float* bq = (const float*)d_in[9];
    const float* Wk = (const float*)d_in[10];
    const float* bk = (const float*)d_in[11];
    const float* Wv = (const float*)d_in[12];
    const float* bv = (const float*)d_in[13];
    const float* Wo = (const float*)d_in[14];
    const float* bo = (const float*)d_in[15];
    const float* ln1_g = (const float*)d_in[16];
    const float* ln1_b = (const float*)d_in[17];
    const float* W1 = (const float*)d_in[18];
    const float* b1 = (const float*)d_in[19];
    const float* W2 = (const float*)d_in[20];
    const float* b2 = (const float*)d_in[21];
    const float* ln2_g = (const float*)d_in[22];
    const float* ln2_b = (const float*)d_in[23];
    const float* W_concept = (const float*)d_in[24];
    const float* b_concept = (const float*)d_in[25];
    const float* W_out = (const float*)d_in[26];
    const float* b_out = (const float*)d_in[27];

    float *x, *q, *k, *v, *ao, *ffn, *part;
    cudaGetSymbolAddress((void**)&x, g_x);
    cudaGetSymbolAddress((void**)&q, g_q);
    cudaGetSymbolAddress((void**)&k, g_k);
    cudaGetSymbolAddress((void**)&v, g_v);
    cudaGetSymbolAddress((void**)&ao, g_ao);
    cudaGetSymbolAddress((void**)&ffn, g_ffn);
    cudaGetSymbolAddress((void**)&part, g_part);

    const int M = S_TOK;
    const dim3 blk(256);
    const int MT = (M + 63) / 64;                 // 5 m-tiles
    const dim3 grid_qkv(D_DIM / 64, MT, 3);       // 240 blocks
    const dim3 grid_o(D_DIM / 64, MT, 2);         // split-K=2, 160 blocks
    const dim3 grid_w1(HID / 64, MT, 1);          // 320 blocks
    const dim3 grid_w2(D_DIM / 64, MT, 4);        // split-K=4, 320 blocks
    const dim3 grid_attn(HEADS, (S_TOK + 31) / 32);   // 16 x 9

    // --- embeddings ---
    matvec_kernel<<<D_DIM / 8, 256>>>(W_core, b_core, observation, x, D_DIM, OBS_N, 0);
    cemb_kernel<<<NC, 256>>>(concepts, W_cemb, b_cemb, W_age, b_age, x);

    // --- transformer layers ---
    for (int l = 0; l < NLAYER; l++) {
        const size_t od  = (size_t)l * D_DIM * D_DIM;
        const size_t ob  = (size_t)l * D_DIM;
        const size_t o1w = (size_t)l * HID * D_DIM;
        const size_t o1b = (size_t)l * HID;

        gemm_qkv_kernel<<<grid_qkv, blk>>>(x, Wq + od, Wk + od, Wv + od,
                                           bq + ob, bk + ob, bv + ob,
                                           q, k, v, M, D_DIM, D_DIM);

        attn2_kernel<<<grid_attn, blk>>>(q, k, v, ao);

        gemm_splitk_kernel<<<grid_o, blk>>>(ao, Wo + od, part, M, D_DIM, D_DIM, D_DIM / 2);
        combine_ln_kernel<<<M, 256>>>(part, 2, bo + ob, x, ln1_g + ob, ln1_b + ob, x, M);

        gemm_direct_kernel<<<grid_w1, blk>>>(x, W1 + o1w, b1 + o1b, ffn, M, HID, D_DIM, 1);
        gemm_splitk_kernel<<<grid_w2, blk>>>(ffn, W2 + o1w, part, M, D_DIM, HID, HID / 4);
        combine_ln_kernel<<<M, 256>>>(part, 4, b2 + ob, x, ln2_g + ob, ln2_b + ob, x, M);
    }

    // --- heads (node 0) -> d_out = [output(512) | new_concept(128)] ---
    float* out = (float*)d_out;
    matvec_kernel<<<OUT_N / 8, 256>>>(W_out, b_out, x, out, OUT_N, D_DIM, 1);
    matvec_kernel<<<CSZ / 8, 256>>>(W_concept, b_concept, x, out + OUT_N, CSZ, D_DIM, 2);

    (void)in_sizes; (void)n_in; (void)out_size;
}